// round 1
// baseline (speedup 1.0000x reference)
#include <cuda_runtime.h>
#include <cstdint>

// ---------------------------------------------------------------------------
// Problem constants (fixed shapes from reference)
// ---------------------------------------------------------------------------
constexpr int Bb = 2, Tt = 256, Mm = 80, Dd = 512;
constexpr int NT = Bb * Tt * Mm;   // 40960 tokens
constexpr int G3 = 3 * Dd;         // 1536
constexpr int NSEQ_T = Bb * Mm;    // 160 time-GRU sequences
constexpr int NSEQ_F = Bb * Tt;    // 512 freq-GRU sequences

// ---------------------------------------------------------------------------
// Scratch (static device memory; no runtime allocation allowed)
// ---------------------------------------------------------------------------
__device__ float g_gi_t[(size_t)NT * G3];   // time GRU input projections
__device__ float g_gi_f[(size_t)NT * G3];   // freq fwd GRU input projections
__device__ float g_gi_b[(size_t)NT * G3];   // freq bwd GRU input projections
__device__ float g_gi_s[(size_t)NT * G3];   // stack GRU input projections
__device__ float g_xcat[(size_t)NT * G3];   // concat(x1, fwd, bwd)
__device__ float g_xs[(size_t)NT * Dd];     // stack GRU outputs
__device__ float g_h0[NSEQ_F * Dd];         // hidden ping/pong buffers
__device__ float g_h1[NSEQ_F * Dd];
__device__ float g_h2[NSEQ_F * Dd];
__device__ float g_h3[NSEQ_F * Dd];

// ---------------------------------------------------------------------------
// Generic GEMM:  C[Mr,N] = (A (+A2))[Mr,K] @ W[N,K]^T + bias[N] (+ res[Mr,N])
// BM=128, BN=64, BK=16, 256 threads, 8x4 per-thread tile.
// Mr is implied by gridDim.y*128 (all our Mr = 40960, divisible).
// ---------------------------------------------------------------------------
__global__ __launch_bounds__(256) void gemm_tn(
    const float* __restrict__ A, const float* __restrict__ A2,
    const float* __restrict__ W, const float* __restrict__ bias,
    const float* __restrict__ res, float* __restrict__ C,
    int K, int N)
{
    __shared__ float As[16][132];  // [k][row], padded
    __shared__ float Ws[16][68];   // [k][col], padded

    const int tid = threadIdx.x;
    const int row0 = blockIdx.y * 128;
    const int col0 = blockIdx.x * 64;
    const int tx = tid & 15;   // 16 col groups * 4 cols
    const int ty = tid >> 4;   // 16 row groups * 8 rows

    float acc[8][4];
#pragma unroll
    for (int i = 0; i < 8; i++)
#pragma unroll
        for (int j = 0; j < 4; j++) acc[i][j] = 0.f;

    for (int k0 = 0; k0 < K; k0 += 16) {
        // load A tile (128x16), 2 float4 per thread, transpose into smem
#pragma unroll
        for (int i = 0; i < 2; i++) {
            int idx = tid * 2 + i;          // 0..511
            int r = idx >> 2;               // 0..127
            int c4 = (idx & 3) * 4;         // 0,4,8,12
            float4 v = *reinterpret_cast<const float4*>(
                A + (size_t)(row0 + r) * K + k0 + c4);
            if (A2) {
                float4 w = *reinterpret_cast<const float4*>(
                    A2 + (size_t)(row0 + r) * K + k0 + c4);
                v.x += w.x; v.y += w.y; v.z += w.z; v.w += w.w;
            }
            As[c4 + 0][r] = v.x; As[c4 + 1][r] = v.y;
            As[c4 + 2][r] = v.z; As[c4 + 3][r] = v.w;
        }
        // load W tile (64x16), 1 float4 per thread
        {
            int r = tid >> 2;               // 0..63
            int c4 = (tid & 3) * 4;
            float4 v = *reinterpret_cast<const float4*>(
                W + (size_t)(col0 + r) * K + k0 + c4);
            Ws[c4 + 0][r] = v.x; Ws[c4 + 1][r] = v.y;
            Ws[c4 + 2][r] = v.z; Ws[c4 + 3][r] = v.w;
        }
        __syncthreads();

#pragma unroll
        for (int kk = 0; kk < 16; kk++) {
            float a[8], b[4];
            *reinterpret_cast<float4*>(a) =
                *reinterpret_cast<const float4*>(&As[kk][ty * 8]);
            *reinterpret_cast<float4*>(a + 4) =
                *reinterpret_cast<const float4*>(&As[kk][ty * 8 + 4]);
            *reinterpret_cast<float4*>(b) =
                *reinterpret_cast<const float4*>(&Ws[kk][tx * 4]);
#pragma unroll
            for (int i = 0; i < 8; i++)
#pragma unroll
                for (int j = 0; j < 4; j++)
                    acc[i][j] += a[i] * b[j];
        }
        __syncthreads();
    }

#pragma unroll
    for (int i = 0; i < 8; i++) {
        int r = row0 + ty * 8 + i;
#pragma unroll
        for (int j = 0; j < 4; j++) {
            int c = col0 + tx * 4 + j;
            float v = acc[i][j] + bias[c];
            if (res) v += res[(size_t)r * N + c];
            C[(size_t)r * N + c] = v;
        }
    }
}

// ---------------------------------------------------------------------------
// Fused GRU step: gh = h_prev @ W_hh^T (for this block's 32 hidden cols x 3
// gates), then gate nonlinearity + hidden update + output write.
// Block: TS sequences x 32 hidden cols x 3 gates. 256 threads = 8 warps;
// warp w owns sequences [w*SPW, (w+1)*SPW), lane = hidden col within tile.
// gridDim.z selects S0/S1 (used to fuse fwd+bwd freq GRUs in one launch).
// ---------------------------------------------------------------------------
struct GruSet {
    const float* hprev;
    float*       hnext;
    const float* gi;     // (NT, 1536)
    const float* Whh;    // (1536, 512)
    const float* bhh;    // (1536,)
    float*       out;    // output tensor
    int outStride;       // row stride of out
    int outOff;          // column offset within out row
    int mtok;            // m index for freq-mode token computation
};

__device__ __forceinline__ float sigf(float x) {
    return 1.f / (1.f + __expf(-x));
}
__device__ __forceinline__ float tanhfast(float x) {
    // 1 - 2/(e^{2x}+1); saturates correctly at +-1 for |x| large
    float e2x = __expf(2.f * x);
    return 1.f - 2.f / (e2x + 1.f);
}

template <int TS, bool TIME>
__global__ __launch_bounds__(256) void gru_step(GruSet S0, GruSet S1, int t)
{
    const GruSet S = (blockIdx.z == 0) ? S0 : S1;
    constexpr int SPW = TS / 8;  // sequences per warp

    __shared__ float Hs[TS][33];
    __shared__ float Ws[3][32][33];

    const int tid = threadIdx.x;
    const int lane = tid & 31;
    const int warp = tid >> 5;
    const int s0 = blockIdx.x * TS;
    const int j0 = blockIdx.y * 32;

    float accR[SPW], accZ[SPW], accN[SPW];
#pragma unroll
    for (int u = 0; u < SPW; u++) { accR[u] = 0.f; accZ[u] = 0.f; accN[u] = 0.f; }

    for (int k0 = 0; k0 < 512; k0 += 32) {
        // load H tile: TS x 32
        if (tid < TS * 8) {
            int ss = tid >> 3;
            int c4 = (tid & 7) * 4;
            float4 v = *reinterpret_cast<const float4*>(
                S.hprev + (size_t)(s0 + ss) * 512 + k0 + c4);
            Hs[ss][c4 + 0] = v.x; Hs[ss][c4 + 1] = v.y;
            Hs[ss][c4 + 2] = v.z; Hs[ss][c4 + 3] = v.w;
        }
        // load W tiles for the 3 gates: 3 x 32 x 32
        {
            int jj = tid >> 3;
            int c4 = (tid & 7) * 4;
#pragma unroll
            for (int g = 0; g < 3; g++) {
                float4 v = *reinterpret_cast<const float4*>(
                    S.Whh + (size_t)(g * 512 + j0 + jj) * 512 + k0 + c4);
                Ws[g][jj][c4 + 0] = v.x; Ws[g][jj][c4 + 1] = v.y;
                Ws[g][jj][c4 + 2] = v.z; Ws[g][jj][c4 + 3] = v.w;
            }
        }
        __syncthreads();

#pragma unroll
        for (int kk = 0; kk < 32; kk++) {
            float wr = Ws[0][lane][kk];
            float wz = Ws[1][lane][kk];
            float wn = Ws[2][lane][kk];
#pragma unroll
            for (int u = 0; u < SPW; u++) {
                float hv = Hs[warp * SPW + u][kk];
                accR[u] += hv * wr;
                accZ[u] += hv * wz;
                accN[u] += hv * wn;
            }
        }
        __syncthreads();
    }

    const int jc = j0 + lane;
    const float br = S.bhh[jc];
    const float bz = S.bhh[512 + jc];
    const float bn = S.bhh[1024 + jc];

#pragma unroll
    for (int u = 0; u < SPW; u++) {
        int s = s0 + warp * SPW + u;
        int token;
        if (TIME) {
            int b = s / Mm;
            int m = s - b * Mm;
            token = (b * Tt + t) * Mm + m;
        } else {
            token = s * Mm + S.mtok;
        }
        const float* gir = S.gi + (size_t)token * G3;
        float r = sigf(gir[jc] + accR[u] + br);
        float z = sigf(gir[512 + jc] + accZ[u] + bz);
        float n = tanhfast(gir[1024 + jc] + r * (accN[u] + bn));
        float hp = S.hprev[(size_t)s * 512 + jc];
        float hn = (1.f - z) * n + z * hp;
        S.hnext[(size_t)s * 512 + jc] = hn;
        S.out[(size_t)token * S.outStride + S.outOff + jc] = hn;
    }
}

// ---------------------------------------------------------------------------
// Launch
// ---------------------------------------------------------------------------
extern "C" void kernel_launch(void* const* d_in, const int* in_sizes, int n_in,
                              void* d_out_v, int out_size)
{
    const float* x_time = (const float*)d_in[0];
    const float* x_freq = (const float*)d_in[1];
    const float* wt_ih  = (const float*)d_in[2];
    const float* wt_hh  = (const float*)d_in[3];
    const float* bt_ih  = (const float*)d_in[4];
    const float* bt_hh  = (const float*)d_in[5];
    const float* wf_ih  = (const float*)d_in[6];
    const float* wf_hh  = (const float*)d_in[7];
    const float* bf_ih  = (const float*)d_in[8];
    const float* bf_hh  = (const float*)d_in[9];
    const float* wb_ih  = (const float*)d_in[10];
    const float* wb_hh  = (const float*)d_in[11];
    const float* bb_ih  = (const float*)d_in[12];
    const float* bb_hh  = (const float*)d_in[13];
    const float* ws_ih  = (const float*)d_in[14];
    const float* ws_hh  = (const float*)d_in[15];
    const float* bs_ih  = (const float*)d_in[16];
    const float* bs_hh  = (const float*)d_in[17];
    const float* W_time = (const float*)d_in[18];
    const float* b_time = (const float*)d_in[19];
    const float* W_freq = (const float*)d_in[20];
    const float* b_freq = (const float*)d_in[21];
    float* dout = (float*)d_out_v;

    float *gi_t, *gi_f, *gi_b, *gi_s, *xcat, *xs, *h0, *h1, *h2, *h3;
    cudaGetSymbolAddress((void**)&gi_t, g_gi_t);
    cudaGetSymbolAddress((void**)&gi_f, g_gi_f);
    cudaGetSymbolAddress((void**)&gi_b, g_gi_b);
    cudaGetSymbolAddress((void**)&gi_s, g_gi_s);
    cudaGetSymbolAddress((void**)&xcat, g_xcat);
    cudaGetSymbolAddress((void**)&xs,   g_xs);
    cudaGetSymbolAddress((void**)&h0,   g_h0);
    cudaGetSymbolAddress((void**)&h1,   g_h1);
    cudaGetSymbolAddress((void**)&h2,   g_h2);
    cudaGetSymbolAddress((void**)&h3,   g_h3);

    const dim3 blk(256);

    // ---- Phase 1: input projections for time / freq-fwd / freq-bwd GRUs ----
    {
        dim3 grid(G3 / 64, NT / 128);
        gemm_tn<<<grid, blk>>>(x_time, nullptr, wt_ih, bt_ih, nullptr, gi_t, Dd, G3);
        gemm_tn<<<grid, blk>>>(x_time, nullptr, wf_ih, bf_ih, nullptr, gi_f, Dd, G3);
        gemm_tn<<<grid, blk>>>(x_time, nullptr, wb_ih, bb_ih, nullptr, gi_b, Dd, G3);
    }

    // ---- Phase 2: time GRU scan (256 steps, 160 sequences) ----
    cudaMemsetAsync(h0, 0, (size_t)NSEQ_T * Dd * sizeof(float));
    for (int t = 0; t < Tt; t++) {
        float* hp = (t & 1) ? h1 : h0;
        float* hn = (t & 1) ? h0 : h1;
        GruSet S{hp, hn, gi_t, wt_hh, bt_hh, xcat, G3, 0, 0};
        gru_step<8, true><<<dim3(NSEQ_T / 8, 16, 1), blk>>>(S, S, t);
    }

    // ---- Phase 3: bidirectional freq GRU scan (80 steps, 512 seqs x 2 dirs) --
    cudaMemsetAsync(h0, 0, (size_t)NSEQ_F * Dd * sizeof(float));
    cudaMemsetAsync(h2, 0, (size_t)NSEQ_F * Dd * sizeof(float));
    for (int s = 0; s < Mm; s++) {
        float* hpF = (s & 1) ? h1 : h0;
        float* hnF = (s & 1) ? h0 : h1;
        float* hpB = (s & 1) ? h3 : h2;
        float* hnB = (s & 1) ? h2 : h3;
        GruSet SF{hpF, hnF, gi_f, wf_hh, bf_hh, xcat, G3, Dd,      s};
        GruSet SB{hpB, hnB, gi_b, wb_hh, bb_hh, xcat, G3, 2 * Dd,  Mm - 1 - s};
        gru_step<32, false><<<dim3(NSEQ_F / 32, 16, 2), blk>>>(SF, SB, 0);
    }

    // ---- Phase 4: xt = xcat @ W_time^T + b_time + x_time  -> dout[0:NT*D] ---
    gemm_tn<<<dim3(Dd / 64, NT / 128), blk>>>(
        xcat, nullptr, W_time, b_time, x_time, dout, G3, Dd);

    // ---- Phase 5: gi_s = (xt + x_freq) @ ws_ih^T + bs_ih ----
    gemm_tn<<<dim3(G3 / 64, NT / 128), blk>>>(
        dout, x_freq, ws_ih, bs_ih, nullptr, gi_s, Dd, G3);

    // ---- Phase 6: stack GRU scan (80 steps, 512 sequences) ----
    cudaMemsetAsync(h0, 0, (size_t)NSEQ_F * Dd * sizeof(float));
    for (int s = 0; s < Mm; s++) {
        float* hp = (s & 1) ? h1 : h0;
        float* hn = (s & 1) ? h0 : h1;
        GruSet S{hp, hn, gi_s, ws_hh, bs_hh, xs, Dd, 0, s};
        gru_step<32, false><<<dim3(NSEQ_F / 32, 16, 1), blk>>>(S, S, 0);
    }

    // ---- Phase 7: xf = xs @ W_freq^T + b_freq + x_freq -> dout[NT*D:] ----
    gemm_tn<<<dim3(Dd / 64, NT / 128), blk>>>(
        xs, nullptr, W_freq, b_freq, x_freq, dout + (size_t)NT * Dd, Dd, Dd);
}